// round 3
// baseline (speedup 1.0000x reference)
#include <cuda_runtime.h>
#include <cuda_bf16.h>
#include <math.h>

#define HDIM 128
#define MAXN 100608
#define NGRAPH 64

// ---------------- device scratch (no allocation allowed) ----------------
__device__ float g_deg[MAXN];              // degree, then deg^-1/2 in-place
__device__ float g_buf0[(size_t)MAXN * HDIM];  // X / AGG buffer
__device__ float g_buf1[(size_t)MAXN * HDIM];  // H (transformed) buffer
__device__ float g_pool[NGRAPH * HDIM];
__device__ float g_cnt[NGRAPH];
__device__ int   g_edge_is64;
__device__ int   g_batch_is64;

// ---------------- index helper: int64 vs int32 storage ----------------
__device__ __forceinline__ long long ld_idx(const void* p, long long i, int is64) {
    if (is64) return ((const long long*)p)[i];
    return (long long)((const int*)p)[i];
}

// ---------------- dtype detection (graph-capturable, device-side) ------
__global__ void detect_kernel(const void* edge, const void* batch) {
    // If the buffer really holds int32, reading as int64 merges two values:
    // lo + hi*2^32 >= 2^32 almost surely (node ids < 2^31). Require all 64
    // probes valid to declare int64.
    const long long* pe = (const long long*)edge;
    int ok = 1;
    for (int i = 0; i < 64; i++) {
        long long v = pe[i];
        if (v < 0 || v >= (1LL << 31)) { ok = 0; break; }
    }
    g_edge_is64 = ok;
    const long long* pb = (const long long*)batch;
    int bok = 1;
    for (int i = 0; i < 64; i++) {
        long long v = pb[i];
        if (v < 0 || v >= (1LL << 31)) { bok = 0; break; }
    }
    g_batch_is64 = bok;
}

// ---------------- degree ----------------
__global__ void init_deg_kernel(int N) {
    int i = blockIdx.x * blockDim.x + threadIdx.x;
    if (i < N) g_deg[i] = 1.0f;   // self-loop contributes 1
}

__global__ void count_deg_kernel(const void* edge, int E) {
    int e = blockIdx.x * blockDim.x + threadIdx.x;
    if (e >= E) return;
    int is64 = g_edge_is64;
    int d = (int)ld_idx(edge, (long long)E + e, is64);   // dst row
    atomicAdd(&g_deg[d], 1.0f);
}

__global__ void dinv_kernel(int N) {
    int i = blockIdx.x * blockDim.x + threadIdx.x;
    if (i < N) g_deg[i] = rsqrtf(g_deg[i]);              // deg >= 1 always
}

// ---------------- layer 1 transform: x=[a,pos] (N,4) @ W0 (4,128) ------
// Fused with self-loop agg init: buf1 = h, buf0 = h * dinv^2
__global__ void transform1_kernel(const float* __restrict__ an,
                                  const float* __restrict__ pos,
                                  const float* __restrict__ W0, int N) {
    int idx = blockIdx.x * blockDim.x + threadIdx.x;
    if (idx >= N * HDIM) return;
    int n = idx >> 7, j = idx & 127;
    float a  = an[n];
    float px = pos[3 * n + 0];
    float py = pos[3 * n + 1];
    float pz = pos[3 * n + 2];
    float h = a * W0[j] + px * W0[HDIM + j] + py * W0[2 * HDIM + j]
            + pz * W0[3 * HDIM + j];
    g_buf1[idx] = h;
    float dn = g_deg[n];
    g_buf0[idx] = h * dn * dn;
}

// ---------------- edge aggregation: warp per edge, float4 vector red ----
__global__ void __launch_bounds__(256) edge_agg_kernel(const void* edge, int E) {
    int gtid = blockIdx.x * blockDim.x + threadIdx.x;
    int e    = gtid >> 5;
    int lane = threadIdx.x & 31;
    if (e >= E) return;
    int is64 = g_edge_is64;
    long long s = ld_idx(edge, e, is64);
    long long d = ld_idx(edge, (long long)E + e, is64);
    float w = g_deg[s] * g_deg[d];
    const float4* srcp = (const float4*)&g_buf1[s * HDIM];
    float4 v = srcp[lane];
    v.x *= w; v.y *= w; v.z *= w; v.w *= w;
    float* dstp = &g_buf0[d * HDIM + lane * 4];
    asm volatile("red.global.add.v4.f32 [%0], {%1,%2,%3,%4};"
                 :: "l"(dstp), "f"(v.x), "f"(v.y), "f"(v.z), "f"(v.w)
                 : "memory");
}

// ---------------- bias + relu, in place on buf0 ----------------
__global__ void bias_relu_kernel(const float* __restrict__ b, int N) {
    int idx = blockIdx.x * blockDim.x + threadIdx.x;
    if (idx >= N * HDIM) return;
    int j = idx & 127;
    float v = g_buf0[idx] + b[j];
    g_buf0[idx] = v > 0.0f ? v : 0.0f;
}

// ---------------- layers 2/3 transform: (N,128)@(128,128) fp32 ---------
// Reads X from buf0, writes H to buf1 and self-loop init back into buf0.
// Safe: each block only reads/writes its own 16 node rows of buf0.
#define NPB 16
__global__ void __launch_bounds__(128) gemm_kernel(const float* __restrict__ W, int N) {
    __shared__ float Xs[NPB][HDIM];
    int n0 = blockIdx.x * NPB;
    int j  = threadIdx.x;            // output column
    #pragma unroll
    for (int r = 0; r < NPB; r++) {
        int n = n0 + r;
        Xs[r][j] = (n < N) ? g_buf0[(size_t)n * HDIM + j] : 0.0f;
    }
    __syncthreads();
    float acc[NPB];
    #pragma unroll
    for (int r = 0; r < NPB; r++) acc[r] = 0.0f;
    #pragma unroll 4
    for (int k = 0; k < HDIM; k++) {
        float w = W[k * HDIM + j];
        #pragma unroll
        for (int r = 0; r < NPB; r++) acc[r] += Xs[r][k] * w;
    }
    #pragma unroll
    for (int r = 0; r < NPB; r++) {
        int n = n0 + r;
        if (n < N) {
            float h = acc[r];
            g_buf1[(size_t)n * HDIM + j] = h;
            float dn = g_deg[n];
            g_buf0[(size_t)n * HDIM + j] = h * dn * dn;
        }
    }
}

// ---------------- pooling ----------------
__global__ void pool_zero_kernel() {
    int i = blockIdx.x * blockDim.x + threadIdx.x;
    if (i < NGRAPH * HDIM) g_pool[i] = 0.0f;
    if (i < NGRAPH) g_cnt[i] = 0.0f;
}

// batch is sorted: accumulate runs in registers, flush atomics at
// graph boundaries only.
#define POOL_NODES 512
__global__ void __launch_bounds__(128) pool_acc_kernel(const void* batch, int N) {
    int j  = threadIdx.x;            // 128 columns
    int n0 = blockIdx.x * POOL_NODES;
    int n1 = min(n0 + POOL_NODES, N);
    int is64 = g_batch_is64;
    float acc = 0.0f, cnt = 0.0f;
    int cur = -1;
    for (int n = n0; n < n1; n++) {
        int g = (int)ld_idx(batch, n, is64);
        if (g != cur) {
            if (cur >= 0) {
                atomicAdd(&g_pool[cur * HDIM + j], acc);
                if (j == 0) atomicAdd(&g_cnt[cur], cnt);
            }
            cur = g; acc = 0.0f; cnt = 0.0f;
        }
        acc += g_buf0[(size_t)n * HDIM + j];
        cnt += 1.0f;
    }
    if (cur >= 0) {
        atomicAdd(&g_pool[cur * HDIM + j], acc);
        if (j == 0) atomicAdd(&g_cnt[cur], cnt);
    }
}

// ---------------- head: mean, linear(128->8), softmax ----------------
__global__ void final_kernel(const float* __restrict__ linW,
                             const float* __restrict__ linb,
                             float* __restrict__ out) {
    int t = threadIdx.x;             // 512 = 64 graphs * 8 experts
    int g = t >> 3, e = t & 7;
    float c = fmaxf(g_cnt[g], 1.0f);
    float acc = 0.0f;
    #pragma unroll 8
    for (int k = 0; k < HDIM; k++)
        acc += g_pool[g * HDIM + k] * linW[k * 8 + e];
    float logit = acc / c + linb[e];
    // softmax within each 8-lane group (lanes g*8+e; xor 4,2,1 stays in group)
    float m = logit;
    for (int o = 4; o >= 1; o >>= 1)
        m = fmaxf(m, __shfl_xor_sync(0xFFFFFFFFu, m, o));
    float ex = expf(logit - m);
    float s = ex;
    for (int o = 4; o >= 1; o >>= 1)
        s += __shfl_xor_sync(0xFFFFFFFFu, s, o);
    out[t] = ex / s;
}

// ---------------- launch ----------------
extern "C" void kernel_launch(void* const* d_in, const int* in_sizes, int n_in,
                              void* d_out, int out_size) {
    const float* an   = (const float*)d_in[0];
    const float* pos  = (const float*)d_in[1];
    const float* W0   = (const float*)d_in[2];
    const float* b0   = (const float*)d_in[3];
    const float* W1   = (const float*)d_in[4];
    const float* b1   = (const float*)d_in[5];
    const float* W2   = (const float*)d_in[6];
    const float* b2   = (const float*)d_in[7];
    const float* linW = (const float*)d_in[8];
    const float* linb = (const float*)d_in[9];
    const void*  edge = d_in[10];
    const void*  batch= d_in[11];
    int N = in_sizes[0];
    int E = in_sizes[10] / 2;
    float* out = (float*)d_out;

    detect_kernel<<<1, 1>>>(edge, batch);
    init_deg_kernel<<<(N + 255) / 256, 256>>>(N);
    count_deg_kernel<<<(E + 255) / 256, 256>>>(edge, E);
    dinv_kernel<<<(N + 255) / 256, 256>>>(N);

    int nh = N * HDIM;
    // layer 1
    transform1_kernel<<<(nh + 255) / 256, 256>>>(an, pos, W0, N);
    edge_agg_kernel<<<(int)(((long long)E * 32 + 255) / 256), 256>>>(edge, E);
    bias_relu_kernel<<<(nh + 255) / 256, 256>>>(b0, N);
    // layer 2
    gemm_kernel<<<(N + NPB - 1) / NPB, 128>>>(W1, N);
    edge_agg_kernel<<<(int)(((long long)E * 32 + 255) / 256), 256>>>(edge, E);
    bias_relu_kernel<<<(nh + 255) / 256, 256>>>(b1, N);
    // layer 3
    gemm_kernel<<<(N + NPB - 1) / NPB, 128>>>(W2, N);
    edge_agg_kernel<<<(int)(((long long)E * 32 + 255) / 256), 256>>>(edge, E);
    bias_relu_kernel<<<(nh + 255) / 256, 256>>>(b2, N);
    // pool + head
    pool_zero_kernel<<<(NGRAPH * HDIM + 255) / 256, 256>>>();
    pool_acc_kernel<<<(N + POOL_NODES - 1) / POOL_NODES, 128>>>(batch, N);
    final_kernel<<<1, 512>>>(linW, linb, out);
}

// round 5
// speedup vs baseline: 1.4191x; 1.4191x over previous
#include <cuda_runtime.h>
#include <cuda_bf16.h>
#include <math.h>

#define HDIM 128
#define MAXN 100608
#define MAXE 1700000
#define NGRAPH 64

// ---------------- device scratch (no allocation allowed) ----------------
__device__ float g_deg[MAXN];                  // dinv = 1/sqrt(deg)
__device__ int   g_degi[MAXN];                 // in-degree (without self loop)
__device__ int   g_off[MAXN];                  // CSR offsets (exclusive scan)
__device__ int   g_cursor[MAXN];               // scatter cursors
__device__ int   g_blocksum[128];              // scan partials
__device__ int2  g_csr[MAXE];                  // {src, dinv[src] as bits}
__device__ float g_buf0[(size_t)MAXN * HDIM];  // X / AGG buffer
__device__ float g_buf1[(size_t)MAXN * HDIM];  // H (transformed) buffer
__device__ float g_pool[NGRAPH * HDIM];
__device__ float g_cnt[NGRAPH];
__device__ int   g_edge_is64;
__device__ int   g_batch_is64;

// ---------------- index helper: int64 vs int32 storage ----------------
__device__ __forceinline__ long long ld_idx(const void* p, long long i, int is64) {
    if (is64) return ((const long long*)p)[i];
    return (long long)((const int*)p)[i];
}

// ---------------- dtype detection (graph-capturable, device-side) ------
__global__ void detect_kernel(const void* edge, const void* batch) {
    const long long* pe = (const long long*)edge;
    int ok = 1;
    for (int i = 0; i < 64; i++) {
        long long v = pe[i];
        if (v < 0 || v >= (1LL << 31)) { ok = 0; break; }
    }
    g_edge_is64 = ok;
    const long long* pb = (const long long*)batch;
    int bok = 1;
    for (int i = 0; i < 64; i++) {
        long long v = pb[i];
        if (v < 0 || v >= (1LL << 31)) { bok = 0; break; }
    }
    g_batch_is64 = bok;
}

// ---------------- degree / norm ----------------
__global__ void zero_deg_kernel(int N) {
    int i = blockIdx.x * blockDim.x + threadIdx.x;
    if (i < N) { g_degi[i] = 0; g_cursor[i] = 0; }
}

__global__ void count_deg_kernel(const void* edge, int E) {
    int e = blockIdx.x * blockDim.x + threadIdx.x;
    if (e >= E) return;
    int is64 = g_edge_is64;
    int d = (int)ld_idx(edge, (long long)E + e, is64);
    atomicAdd(&g_degi[d], 1);
}

__global__ void dinv_kernel(int N) {
    int i = blockIdx.x * blockDim.x + threadIdx.x;
    if (i < N) g_deg[i] = (float)(1.0 / sqrt((double)(g_degi[i] + 1)));
}

// ---------------- exclusive prefix scan of g_degi -> g_off ----------------
// 1024 items per block (256 threads x 4)
__global__ void __launch_bounds__(256) scan1_kernel(int N) {
    __shared__ int sh[256];
    int t = threadIdx.x;
    int base = blockIdx.x * 1024 + t * 4;
    int v0 = (base + 0 < N) ? g_degi[base + 0] : 0;
    int v1 = (base + 1 < N) ? g_degi[base + 1] : 0;
    int v2 = (base + 2 < N) ? g_degi[base + 2] : 0;
    int v3 = (base + 3 < N) ? g_degi[base + 3] : 0;
    int sum = v0 + v1 + v2 + v3;
    sh[t] = sum;
    __syncthreads();
    for (int o = 1; o < 256; o <<= 1) {
        int x = (t >= o) ? sh[t - o] : 0;
        __syncthreads();
        sh[t] += x;
        __syncthreads();
    }
    if (t == 255) g_blocksum[blockIdx.x] = sh[255];
    int run = sh[t] - sum;
    if (base + 0 < N) { g_off[base + 0] = run; run += v0; }
    if (base + 1 < N) { g_off[base + 1] = run; run += v1; }
    if (base + 2 < N) { g_off[base + 2] = run; run += v2; }
    if (base + 3 < N) { g_off[base + 3] = run; }
}

__global__ void scan2_kernel(int nb) {
    __shared__ int sh[128];
    int t = threadIdx.x;
    int v = (t < nb) ? g_blocksum[t] : 0;
    sh[t] = v;
    __syncthreads();
    for (int o = 1; o < 128; o <<= 1) {
        int x = (t >= o) ? sh[t - o] : 0;
        __syncthreads();
        sh[t] += x;
        __syncthreads();
    }
    g_blocksum[t] = sh[t] - v;   // exclusive block offsets
}

__global__ void scan3_kernel(int N) {
    int i = blockIdx.x * blockDim.x + threadIdx.x;
    if (i < N) g_off[i] += g_blocksum[i >> 10];
}

// ---------------- CSR scatter ----------------
__global__ void scatter_kernel(const void* edge, int E) {
    int e = blockIdx.x * blockDim.x + threadIdx.x;
    if (e >= E) return;
    int is64 = g_edge_is64;
    int s = (int)ld_idx(edge, e, is64);
    int d = (int)ld_idx(edge, (long long)E + e, is64);
    int pos = atomicAdd(&g_cursor[d], 1);
    int2 ent;
    ent.x = s;
    ent.y = __float_as_int(g_deg[s]);
    g_csr[g_off[d] + pos] = ent;
}

// ---------------- layer 1 transform: x=[a,pos] (N,4) @ W0 (4,128) ------
__global__ void transform1_kernel(const float* __restrict__ an,
                                  const float* __restrict__ pos,
                                  const float* __restrict__ W0, int N) {
    int idx = blockIdx.x * blockDim.x + threadIdx.x;
    if (idx >= N * HDIM) return;
    int n = idx >> 7, j = idx & 127;
    float a  = an[n];
    float px = pos[3 * n + 0];
    float py = pos[3 * n + 1];
    float pz = pos[3 * n + 2];
    g_buf1[idx] = a * W0[j] + px * W0[HDIM + j] + py * W0[2 * HDIM + j]
                + pz * W0[3 * HDIM + j];
}

// ---------------- fused aggregation + self-loop + bias + relu ----------
// One warp per dst node. Lane l handles float4 at column l*4.
// out[d] = relu( dinv[d]*( sum_e dinv[s_e]*h[s_e] + dinv[d]*h[d] ) + b )
__global__ void __launch_bounds__(256) agg_kernel(const float* __restrict__ bias, int N) {
    int warp = (blockIdx.x * 256 + threadIdx.x) >> 5;
    int lane = threadIdx.x & 31;
    if (warp >= N) return;
    int d   = warp;
    int off = g_off[d];
    int deg = g_degi[d];
    float dn = g_deg[d];

    float4 h = ((const float4*)&g_buf1[(size_t)d * HDIM])[lane];
    float4 acc;
    acc.x = h.x * dn; acc.y = h.y * dn; acc.z = h.z * dn; acc.w = h.w * dn;

    int end = off + deg;
    int e0 = off;
    // main loop: 4 independent gathers in flight
    for (; e0 + 4 <= end; e0 += 4) {
        int2 en0 = g_csr[e0 + 0];
        int2 en1 = g_csr[e0 + 1];
        int2 en2 = g_csr[e0 + 2];
        int2 en3 = g_csr[e0 + 3];
        float4 v0 = ((const float4*)&g_buf1[(size_t)en0.x * HDIM])[lane];
        float4 v1 = ((const float4*)&g_buf1[(size_t)en1.x * HDIM])[lane];
        float4 v2 = ((const float4*)&g_buf1[(size_t)en2.x * HDIM])[lane];
        float4 v3 = ((const float4*)&g_buf1[(size_t)en3.x * HDIM])[lane];
        float w0 = __int_as_float(en0.y), w1 = __int_as_float(en1.y);
        float w2 = __int_as_float(en2.y), w3 = __int_as_float(en3.y);
        acc.x += w0 * v0.x; acc.y += w0 * v0.y; acc.z += w0 * v0.z; acc.w += w0 * v0.w;
        acc.x += w1 * v1.x; acc.y += w1 * v1.y; acc.z += w1 * v1.z; acc.w += w1 * v1.w;
        acc.x += w2 * v2.x; acc.y += w2 * v2.y; acc.z += w2 * v2.z; acc.w += w2 * v2.w;
        acc.x += w3 * v3.x; acc.y += w3 * v3.y; acc.z += w3 * v3.z; acc.w += w3 * v3.w;
    }
    for (; e0 < end; e0++) {
        int2 en = g_csr[e0];
        float4 v = ((const float4*)&g_buf1[(size_t)en.x * HDIM])[lane];
        float w = __int_as_float(en.y);
        acc.x += w * v.x; acc.y += w * v.y; acc.z += w * v.z; acc.w += w * v.w;
    }

    float4 b = ((const float4*)bias)[lane];
    float4 r;
    r.x = fmaxf(acc.x * dn + b.x, 0.0f);
    r.y = fmaxf(acc.y * dn + b.y, 0.0f);
    r.z = fmaxf(acc.z * dn + b.z, 0.0f);
    r.w = fmaxf(acc.w * dn + b.w, 0.0f);
    ((float4*)&g_buf0[(size_t)d * HDIM])[lane] = r;
}

// ---------------- layers 2/3 transform: (N,128)@(128,128) fp32 ---------
// Reads X from buf0, writes H to buf1 only.
#define NPB 16
__global__ void __launch_bounds__(128) gemm_kernel(const float* __restrict__ W, int N) {
    __shared__ float Xs[NPB * HDIM];
    int n0 = blockIdx.x * NPB;
    int j  = threadIdx.x;
    #pragma unroll
    for (int r = 0; r < NPB; r++) {
        int n = n0 + r;
        Xs[r * HDIM + j] = (n < N) ? g_buf0[(size_t)n * HDIM + j] : 0.0f;
    }
    __syncthreads();
    float acc[NPB];
    #pragma unroll
    for (int r = 0; r < NPB; r++) acc[r] = 0.0f;
    #pragma unroll 2
    for (int k4 = 0; k4 < HDIM / 4; k4++) {
        float w0 = W[(k4 * 4 + 0) * HDIM + j];
        float w1 = W[(k4 * 4 + 1) * HDIM + j];
        float w2 = W[(k4 * 4 + 2) * HDIM + j];
        float w3 = W[(k4 * 4 + 3) * HDIM + j];
        #pragma unroll
        for (int r = 0; r < NPB; r++) {
            float4 x = *(const float4*)&Xs[r * HDIM + k4 * 4];
            acc[r] += x.x * w0;
            acc[r] += x.y * w1;
            acc[r] += x.z * w2;
            acc[r] += x.w * w3;
        }
    }
    #pragma unroll
    for (int r = 0; r < NPB; r++) {
        int n = n0 + r;
        if (n < N) g_buf1[(size_t)n * HDIM + j] = acc[r];
    }
}

// ---------------- pooling ----------------
__global__ void pool_zero_kernel() {
    int i = blockIdx.x * blockDim.x + threadIdx.x;
    if (i < NGRAPH * HDIM) g_pool[i] = 0.0f;
    if (i < NGRAPH) g_cnt[i] = 0.0f;
}

// batch is sorted: accumulate runs in (double) registers, flush atomics at
// graph boundaries only.
#define POOL_NODES 512
__global__ void __launch_bounds__(128) pool_acc_kernel(const void* batch, int N) {
    int j  = threadIdx.x;
    int n0 = blockIdx.x * POOL_NODES;
    int n1 = min(n0 + POOL_NODES, N);
    int is64 = g_batch_is64;
    double acc = 0.0;
    float cnt = 0.0f;
    int cur = -1;
    for (int n = n0; n < n1; n++) {
        int g = (int)ld_idx(batch, n, is64);
        if (g != cur) {
            if (cur >= 0) {
                atomicAdd(&g_pool[cur * HDIM + j], (float)acc);
                if (j == 0) atomicAdd(&g_cnt[cur], cnt);
            }
            cur = g; acc = 0.0; cnt = 0.0f;
        }
        acc += (double)g_buf0[(size_t)n * HDIM + j];
        cnt += 1.0f;
    }
    if (cur >= 0) {
        atomicAdd(&g_pool[cur * HDIM + j], (float)acc);
        if (j == 0) atomicAdd(&g_cnt[cur], cnt);
    }
}

// ---------------- head: mean, linear(128->8), softmax (double) ---------
__global__ void final_kernel(const float* __restrict__ linW,
                             const float* __restrict__ linb,
                             float* __restrict__ out) {
    int t = threadIdx.x;             // 512 = 64 graphs * 8 experts
    int g = t >> 3, e = t & 7;
    double c = (double)fmaxf(g_cnt[g], 1.0f);
    double acc = 0.0;
    #pragma unroll 8
    for (int k = 0; k < HDIM; k++)
        acc += (double)g_pool[g * HDIM + k] * (double)linW[k * 8 + e];
    double logit = acc / c + (double)linb[e];
    double m = logit;
    for (int o = 4; o >= 1; o >>= 1) {
        double other = __shfl_xor_sync(0xFFFFFFFFu, m, o);
        m = fmax(m, other);
    }
    double ex = exp(logit - m);
    double s = ex;
    for (int o = 4; o >= 1; o >>= 1)
        s += __shfl_xor_sync(0xFFFFFFFFu, s, o);
    out[t] = (float)(ex / s);
}

// ---------------- launch ----------------
extern "C" void kernel_launch(void* const* d_in, const int* in_sizes, int n_in,
                              void* d_out, int out_size) {
    const float* an   = (const float*)d_in[0];
    const float* pos  = (const float*)d_in[1];
    const float* W0   = (const float*)d_in[2];
    const float* b0   = (const float*)d_in[3];
    const float* W1   = (const float*)d_in[4];
    const float* b1   = (const float*)d_in[5];
    const float* W2   = (const float*)d_in[6];
    const float* b2   = (const float*)d_in[7];
    const float* linW = (const float*)d_in[8];
    const float* linb = (const float*)d_in[9];
    const void*  edge = d_in[10];
    const void*  batch= d_in[11];
    int N = in_sizes[0];
    int E = in_sizes[10] / 2;
    float* out = (float*)d_out;

    // prologue: degrees, norms, CSR
    detect_kernel<<<1, 1>>>(edge, batch);
    zero_deg_kernel<<<(N + 255) / 256, 256>>>(N);
    count_deg_kernel<<<(E + 255) / 256, 256>>>(edge, E);
    dinv_kernel<<<(N + 255) / 256, 256>>>(N);
    int nb = (N + 1023) / 1024;
    scan1_kernel<<<nb, 256>>>(N);
    scan2_kernel<<<1, 128>>>(nb);
    scan3_kernel<<<(N + 255) / 256, 256>>>(N);
    scatter_kernel<<<(E + 255) / 256, 256>>>(edge, E);

    int nh = N * HDIM;
    int agg_grid = (N + 7) / 8;
    // layer 1
    transform1_kernel<<<(nh + 255) / 256, 256>>>(an, pos, W0, N);
    agg_kernel<<<agg_grid, 256>>>(b0, N);
    // layer 2
    gemm_kernel<<<(N + NPB - 1) / NPB, 128>>>(W1, N);
    agg_kernel<<<agg_grid, 256>>>(b1, N);
    // layer 3
    gemm_kernel<<<(N + NPB - 1) / NPB, 128>>>(W2, N);
    agg_kernel<<<agg_grid, 256>>>(b2, N);
    // pool + head
    pool_zero_kernel<<<(NGRAPH * HDIM + 255) / 256, 256>>>();
    pool_acc_kernel<<<(N + POOL_NODES - 1) / POOL_NODES, 128>>>(batch, N);
    final_kernel<<<1, 512>>>(linW, linb, out);
}